// round 3
// baseline (speedup 1.0000x reference)
#include <cuda_runtime.h>

#define NB 8
#define NC 256
#define NN 1024
#define NT 3

// Scratch. Q and V stored TRANSPOSED ([n][c]) so the attention kernel's fills
// are conflict-free coalesced float4 copies. K stays [c][n].
__device__ float g_QpT[NB * NN * NC];            // 8 MB   [b][n][c]
__device__ float g_Kp [NT * NB * NC * NN];       // 24 MB  [t][b][c][n]
__device__ float g_VpT[NT * NB * NN * NC];       // 24 MB  [t][b][n][c]

// ---------------- packed f32x2 helpers ----------------
typedef unsigned long long ull;

__device__ __forceinline__ ull dup2(float v) {
    ull r; asm("mov.b64 %0, {%1,%1};" : "=l"(r) : "f"(v)); return r;
}
__device__ __forceinline__ void fma2(ull& d, ull a, ull b) {
    asm("fma.rn.f32x2 %0, %1, %2, %0;" : "+l"(d) : "l"(a), "l"(b));
}
__device__ __forceinline__ void mul2(ull& d, ull a) {
    asm("mul.rn.f32x2 %0, %0, %1;" : "+l"(d) : "l"(a));
}
__device__ __forceinline__ float2 unpk(ull v) {
    float2 f; asm("mov.b64 {%0,%1}, %2;" : "=f"(f.x), "=f"(f.y) : "l"(v)); return f;
}

// ---------------------------------------------------------------------------
// Projection: dst = W @ X + b.  Block tile 64o x 128n, thread tile 4o x 8n,
// packed FFMA2 over n-pairs. Q and V variants write transposed ([n][c]) via
// scalar STG (scatter is cheap: DRAM ~1%).
// Grid: (NN/128, NC/64, 7*8).  z = proj*8 + b. proj: 0=Q, 1..3=K(t), 4..6=V(t)
// ---------------------------------------------------------------------------
#define XSTR 132

__global__ __launch_bounds__(256) void proj_kernel(
    const float* __restrict__ Wq, const float* __restrict__ bq,
    const float* __restrict__ Wk, const float* __restrict__ bk,
    const float* __restrict__ Wv, const float* __restrict__ bv,
    const float* __restrict__ xs, const float* __restrict__ x0,
    const float* __restrict__ x1, const float* __restrict__ x2)
{
    __shared__ float Ws[64 * 16];
    __shared__ float Xs[16 * XSTR];

    const int tid = threadIdx.x;
    const int tx = tid & 15, og = tid >> 4;
    const int n0 = blockIdx.x * 128;
    const int o0 = blockIdx.y * 64;
    const int z  = blockIdx.z;
    const int p  = z >> 3, b = z & 7;

    const float* W;
    const float* bias;
    const float* X;
    float* dst;
    bool transposed;
    if (p == 0) {
        W = Wq; bias = bq; X = xs + b * NC * NN;
        dst = g_QpT + b * NN * NC; transposed = true;
    } else if (p <= 3) {
        W = Wk; bias = bk;
        const float* tf = (p == 1) ? x0 : ((p == 2) ? x1 : x2);
        X = tf + b * NC * NN;
        dst = g_Kp + ((p - 1) * NB + b) * NC * NN; transposed = false;
    } else {
        W = Wv; bias = bv;
        const float* tf = (p == 4) ? x0 : ((p == 5) ? x1 : x2);
        X = tf + b * NC * NN;
        dst = g_VpT + ((p - 4) * NB + b) * NN * NC; transposed = true;
    }

    ull acc2[4][4];
#pragma unroll
    for (int i = 0; i < 4; i++)
#pragma unroll
        for (int j = 0; j < 4; j++) acc2[i][j] = 0ULL;

    for (int kk = 0; kk < NC; kk += 16) {
        __syncthreads();
        {   // W tile 64x16
            int ol = tid >> 2, cg4 = (tid & 3) * 4;
            *(float4*)&Ws[ol * 16 + cg4] =
                *(const float4*)&W[(o0 + ol) * NC + kk + cg4];
        }
        {   // X tile 16x128
            int cc = tid >> 4, nn8 = (tid & 15) * 8;
            *(float4*)&Xs[cc * XSTR + nn8] =
                *(const float4*)&X[(kk + cc) * NN + n0 + nn8];
            *(float4*)&Xs[cc * XSTR + nn8 + 4] =
                *(const float4*)&X[(kk + cc) * NN + n0 + nn8 + 4];
        }
        __syncthreads();
#pragma unroll
        for (int c4 = 0; c4 < 16; c4 += 4) {
            float4 a4[4];
#pragma unroll
            for (int i = 0; i < 4; i++)
                a4[i] = *(const float4*)&Ws[(og + 16 * i) * 16 + c4];
            ull xp[4][4];
#pragma unroll
            for (int e = 0; e < 4; e++) {
                ulonglong2 k0 = *(const ulonglong2*)&Xs[(c4 + e) * XSTR + tx * 8];
                ulonglong2 k1 = *(const ulonglong2*)&Xs[(c4 + e) * XSTR + tx * 8 + 4];
                xp[e][0] = k0.x; xp[e][1] = k0.y; xp[e][2] = k1.x; xp[e][3] = k1.y;
            }
#pragma unroll
            for (int i = 0; i < 4; i++) {
                const float* af = (const float*)&a4[i];
#pragma unroll
                for (int e = 0; e < 4; e++) {
                    ull ad = dup2(af[e]);
                    fma2(acc2[i][0], ad, xp[e][0]);
                    fma2(acc2[i][1], ad, xp[e][1]);
                    fma2(acc2[i][2], ad, xp[e][2]);
                    fma2(acc2[i][3], ad, xp[e][3]);
                }
            }
        }
    }

#pragma unroll
    for (int i = 0; i < 4; i++) {
        int o = o0 + og + 16 * i;
        float bi = bias[o];
        float v[8];
#pragma unroll
        for (int j = 0; j < 4; j++) {
            float2 f = unpk(acc2[i][j]);
            v[2 * j] = f.x + bi; v[2 * j + 1] = f.y + bi;
        }
        if (!transposed) {
            float4 r0 = {v[0], v[1], v[2], v[3]};
            float4 r1 = {v[4], v[5], v[6], v[7]};
            *(float4*)&dst[o * NN + n0 + tx * 8]     = r0;
            *(float4*)&dst[o * NN + n0 + tx * 8 + 4] = r1;
        } else {
#pragma unroll
            for (int j = 0; j < 8; j++)
                dst[(n0 + tx * 8 + j) * NC + o] = v[j];
        }
    }
}

// ---------------------------------------------------------------------------
// Flash attention, 3 teachers, qtile=64, ktile=128, packed FFMA2.
// Grid 128 = B(8) x qtiles(16). Block 256 (mg=tid&15, qg=tid>>4).
// S: thread 4q x 8m.  PV: thread 4q x 16c (c = mg*4 + 64g).
// ---------------------------------------------------------------------------
#define QSTR 260
#define KSTR 128
#define VSTR 260
#define PSTR 132
#define SSTR 65

#define OFF_Q   0
#define OFF_BIG (64 * QSTR)                 // 16640
#define OFF_P   (OFF_BIG + 256 * KSTR)      // 49408
#define SMEM_FLOATS (OFF_P + 64 * PSTR)     // 57856 floats = 231424 B

__global__ __launch_bounds__(256, 1) void attn_kernel(
    const float* __restrict__ student, float* __restrict__ out)
{
    extern __shared__ float sm[];
    float* Qqs = sm + OFF_Q;     // [64][QSTR]
    float* Big = sm + OFF_BIG;   // K [256][128]  /  V-half [64][VSTR]  /  stage [256][65]
    float* Psm = sm + OFF_P;     // [64][PSTR]

    const int tid = threadIdx.x;
    const int mg = tid & 15, qg = tid >> 4;
    const int b  = blockIdx.x >> 4;
    const int n0 = (blockIdx.x & 15) * 64;

    // Q fill: coalesced float4 copy from g_QpT
    const float* QbT = g_QpT + b * NN * NC;
    for (int r = 0; r < 16; r++) {
        int idx = tid + 256 * r;            // 4096 float4
        int q = idx >> 6, c4 = (idx & 63) * 4;
        *(float4*)&Qqs[q * QSTR + c4] = *(const float4*)&QbT[(n0 + q) * NC + c4];
    }

    const float* stu = student + b * NC * NN;
    float* outb = out + b * NC * NN;

    for (int t = 0; t < NT; t++) {
        const float* Kb  = g_Kp  + (t * NB + b) * NC * NN;
        const float* VbT = g_VpT + (t * NB + b) * NN * NC;

        ull o2[4][8];
#pragma unroll
        for (int i = 0; i < 4; i++)
#pragma unroll
            for (int j = 0; j < 8; j++) o2[i][j] = 0ULL;
        float mrun[4] = {-1e30f, -1e30f, -1e30f, -1e30f};
        float lrun[4] = {0.0f, 0.0f, 0.0f, 0.0f};

        for (int m0 = 0; m0 < NN; m0 += 128) {
            __syncthreads();
            // K fill [256][128]
            for (int r = 0; r < 32; r++) {
                int idx = tid + 256 * r;
                int c = idx >> 5, mq = (idx & 31) * 4;
                *(float4*)&Big[c * KSTR + mq] =
                    *(const float4*)&Kb[c * NN + m0 + mq];
            }
            __syncthreads();

            // S = Q K^T  (4q x 8m per thread, packed pairs over m)
            ull s2[4][4];
#pragma unroll
            for (int i = 0; i < 4; i++)
#pragma unroll
                for (int j = 0; j < 4; j++) s2[i][j] = 0ULL;

#pragma unroll 2
            for (int c4 = 0; c4 < NC; c4 += 4) {
                float4 a4[4];
#pragma unroll
                for (int i = 0; i < 4; i++)
                    a4[i] = *(const float4*)&Qqs[(qg + 16 * i) * QSTR + c4];
                ull kp[4][4];
#pragma unroll
                for (int e = 0; e < 4; e++) {
                    ulonglong2 k0 = *(const ulonglong2*)&Big[(c4 + e) * KSTR + mg * 8];
                    ulonglong2 k1 = *(const ulonglong2*)&Big[(c4 + e) * KSTR + mg * 8 + 4];
                    kp[e][0] = k0.x; kp[e][1] = k0.y; kp[e][2] = k1.x; kp[e][3] = k1.y;
                }
#pragma unroll
                for (int i = 0; i < 4; i++) {
                    const float* af = (const float*)&a4[i];
#pragma unroll
                    for (int e = 0; e < 4; e++) {
                        ull ad = dup2(af[e]);
                        fma2(s2[i][0], ad, kp[e][0]);
                        fma2(s2[i][1], ad, kp[e][1]);
                        fma2(s2[i][2], ad, kp[e][2]);
                        fma2(s2[i][3], ad, kp[e][3]);
                    }
                }
            }

            // online softmax over 128 keys (8 local + 16-lane shuffle groups)
#pragma unroll
            for (int i = 0; i < 4; i++) {
                float sv[8];
#pragma unroll
                for (int j = 0; j < 4; j++) {
                    float2 f = unpk(s2[i][j]);
                    sv[2 * j] = f.x; sv[2 * j + 1] = f.y;
                }
                float tm = sv[0];
#pragma unroll
                for (int j = 1; j < 8; j++) tm = fmaxf(tm, sv[j]);
                tm *= 0.0625f;
#pragma unroll
                for (int d = 1; d < 16; d <<= 1)
                    tm = fmaxf(tm, __shfl_xor_sync(0xffffffffu, tm, d));
                float newm = fmaxf(mrun[i], tm);
                float alpha = __expf(mrun[i] - newm);
                mrun[i] = newm;

                float p[8], ts = 0.0f;
#pragma unroll
                for (int j = 0; j < 8; j++) {
                    p[j] = __expf(sv[j] * 0.0625f - newm);
                    ts += p[j];
                }
#pragma unroll
                for (int d = 1; d < 16; d <<= 1)
                    ts += __shfl_xor_sync(0xffffffffu, ts, d);
                lrun[i] = lrun[i] * alpha + ts;

                float4 p0 = {p[0], p[1], p[2], p[3]};
                float4 p1 = {p[4], p[5], p[6], p[7]};
                *(float4*)&Psm[(qg + 16 * i) * PSTR + mg * 8]     = p0;
                *(float4*)&Psm[(qg + 16 * i) * PSTR + mg * 8 + 4] = p1;

                ull ad = dup2(alpha);
#pragma unroll
                for (int j = 0; j < 8; j++) mul2(o2[i][j], ad);
            }

            // PV in two 64-row V halves staged into Big (K is dead now)
#pragma unroll 1
            for (int h = 0; h < 2; h++) {
                __syncthreads();
                for (int r = 0; r < 16; r++) {
                    int idx = tid + 256 * r;        // 4096 float4 = 64m x 256c
                    int m = idx >> 6, c4 = (idx & 63) * 4;
                    *(float4*)&Big[m * VSTR + c4] =
                        *(const float4*)&VbT[(m0 + h * 64 + m) * NC + c4];
                }
                __syncthreads();

#pragma unroll 2
                for (int m4 = 0; m4 < 64; m4 += 4) {
                    float4 pv4[4];
#pragma unroll
                    for (int i = 0; i < 4; i++)
                        pv4[i] = *(const float4*)&Psm[(qg + 16 * i) * PSTR + h * 64 + m4];
#pragma unroll
                    for (int mm = 0; mm < 4; mm++) {
                        ull vp[8];
#pragma unroll
                        for (int g = 0; g < 4; g++) {
                            ulonglong2 vv = *(const ulonglong2*)
                                &Big[(m4 + mm) * VSTR + mg * 4 + 64 * g];
                            vp[2 * g] = vv.x; vp[2 * g + 1] = vv.y;
                        }
#pragma unroll
                        for (int i = 0; i < 4; i++) {
                            ull ad = dup2(((const float*)&pv4[i])[mm]);
#pragma unroll
                            for (int j = 0; j < 8; j++) fma2(o2[i][j], ad, vp[j]);
                        }
                    }
                }
            }
        } // key tiles

        // epilogue: out += o2 / (3*l), via smem transpose for coalesced gmem
        __syncthreads();
        float* stage = Big;   // [256][SSTR]
#pragma unroll
        for (int i = 0; i < 4; i++) {
            float inv = 1.0f / (3.0f * lrun[i]);
            int q = qg + 16 * i;
#pragma unroll
            for (int g = 0; g < 4; g++)
#pragma unroll
                for (int u = 0; u < 2; u++) {
                    float2 f = unpk(o2[i][2 * g + u]);
                    int c = mg * 4 + 64 * g + 2 * u;
                    stage[c * SSTR + q]       = f.x * inv;
                    stage[(c + 1) * SSTR + q] = f.y * inv;
                }
        }
        __syncthreads();
        for (int r = 0; r < 64; r++) {
            int idx = tid + 256 * r;
            int c = idx >> 6, n = idx & 63;
            int off = c * NN + n0 + n;
            float base = (t == 0) ? stu[off] : outb[off];
            outb[off] = base + stage[c * SSTR + n];
        }
        __syncthreads();
    } // teachers
}

// ---------------------------------------------------------------------------
extern "C" void kernel_launch(void* const* d_in, const int* in_sizes, int n_in,
                              void* d_out, int out_size)
{
    const float* student = (const float*)d_in[0];
    const float* t0 = (const float*)d_in[1];
    const float* t1 = (const float*)d_in[2];
    const float* t2 = (const float*)d_in[3];
    const float* Wq = (const float*)d_in[4];
    const float* bq = (const float*)d_in[5];
    const float* Wk = (const float*)d_in[6];
    const float* bk = (const float*)d_in[7];
    const float* Wv = (const float*)d_in[8];
    const float* bv = (const float*)d_in[9];
    float* out = (float*)d_out;

    dim3 pg(NN / 128, NC / 64, 7 * NB);
    proj_kernel<<<pg, 256>>>(Wq, bq, Wk, bk, Wv, bv, student, t0, t1, t2);

    const int smem_bytes = SMEM_FLOATS * 4;
    cudaFuncSetAttribute(attn_kernel, cudaFuncAttributeMaxDynamicSharedMemorySize,
                         smem_bytes);
    attn_kernel<<<NB * (NN / 64), 256, smem_bytes>>>(student, out);
}

// round 5
// speedup vs baseline: 2.1839x; 2.1839x over previous
#include <cuda_runtime.h>
#include <cstdint>

typedef uint32_t u32;

#define NB 8
#define NC 256
#define NN 1024
#define NT 3

// Scratch: all projected tensors stored TRANSPOSED [.., n, c], tf32-rounded.
__device__ float g_QpT[NB * NN * NC];            // [b][n][c]
__device__ float g_KpT[NT * NB * NN * NC];       // [t][b][n][c]
__device__ float g_VpT[NT * NB * NN * NC];       // [t][b][n][c]

__device__ __forceinline__ u32 to_tf32(float f) {
    u32 r; asm("cvt.rna.tf32.f32 %0, %1;" : "=r"(r) : "f"(f)); return r;
}
__device__ __forceinline__ float rnd_tf32(float f) {
    return __uint_as_float(to_tf32(f));
}

// mma.sync m16n8k8 tf32: D += A*B
__device__ __forceinline__ void mma_tf32(float* d, const u32* a, const u32* b) {
    asm volatile(
        "mma.sync.aligned.m16n8k8.row.col.f32.tf32.tf32.f32 "
        "{%0,%1,%2,%3}, {%4,%5,%6,%7}, {%8,%9}, {%0,%1,%2,%3};"
        : "+f"(d[0]), "+f"(d[1]), "+f"(d[2]), "+f"(d[3])
        : "r"(a[0]), "r"(a[1]), "r"(a[2]), "r"(a[3]), "r"(b[0]), "r"(b[1]));
}

// fast exp: exp2 magic number + deg-5 poly, pure FMA pipe
__device__ __forceinline__ float fast_exp(float x) {
    float t = fmaf(x, 1.4426950408889634f, 12582912.0f);
    float n = t - 12582912.0f;
    int   e = __float_as_int(t) << 23;
    float r = fmaf(x, 1.4426950408889634f, -n);
    float p = 1.3333558146e-3f;
    p = fmaf(p, r, 9.6181291076e-3f);
    p = fmaf(p, r, 5.5504108665e-2f);
    p = fmaf(p, r, 2.4022650696e-1f);
    p = fmaf(p, r, 6.9314718056e-1f);
    p = fmaf(p, r, 1.0f);
    return __int_as_float(__float_as_int(p) + e);
}

// ---------------------------------------------------------------------------
// Projection: dst[n][c_out] = (W @ X + b)^T, tf32-rounded.
// Grid: (NN/64, NC/64, 7*8). z = proj*8 + b. proj: 0=Q, 1..3=K(t), 4..6=V(t)
// ---------------------------------------------------------------------------
__global__ __launch_bounds__(256) void proj_kernel(
    const float* __restrict__ Wq, const float* __restrict__ bq,
    const float* __restrict__ Wk, const float* __restrict__ bk,
    const float* __restrict__ Wv, const float* __restrict__ bv,
    const float* __restrict__ xs, const float* __restrict__ x0,
    const float* __restrict__ x1, const float* __restrict__ x2)
{
    __shared__ float Ws[64 * 16];
    __shared__ float Xs[16 * 64];
    __shared__ float stage[64 * 68];

    const int tid = threadIdx.x;
    const int tx = tid & 15, ty = tid >> 4;
    const int n0 = blockIdx.x * 64;
    const int o0 = blockIdx.y * 64;
    const int z  = blockIdx.z;
    const int p  = z >> 3, b = z & 7;

    const float* W; const float* bias; const float* X; float* dst;
    if (p == 0) {
        W = Wq; bias = bq; X = xs + b * NC * NN;
        dst = g_QpT + (size_t)b * NN * NC;
    } else if (p <= 3) {
        W = Wk; bias = bk;
        const float* tf = (p == 1) ? x0 : ((p == 2) ? x1 : x2);
        X = tf + b * NC * NN;
        dst = g_KpT + ((size_t)(p - 1) * NB + b) * NN * NC;
    } else {
        W = Wv; bias = bv;
        const float* tf = (p == 4) ? x0 : ((p == 5) ? x1 : x2);
        X = tf + b * NC * NN;
        dst = g_VpT + ((size_t)(p - 4) * NB + b) * NN * NC;
    }

    float acc[4][4];
#pragma unroll
    for (int i = 0; i < 4; i++)
#pragma unroll
        for (int j = 0; j < 4; j++) acc[i][j] = 0.0f;

    for (int kk = 0; kk < NC; kk += 16) {
        __syncthreads();
        {
            int ol = tid >> 2, cg4 = (tid & 3) * 4;
            *(float4*)&Ws[ol * 16 + cg4] = *(const float4*)&W[(o0 + ol) * NC + kk + cg4];
        }
        {
            int cc = tid >> 4, ng = tid & 15;
            *(float4*)&Xs[cc * 64 + ng * 4] = *(const float4*)&X[(kk + cc) * NN + n0 + ng * 4];
        }
        __syncthreads();
#pragma unroll
        for (int c4 = 0; c4 < 16; c4 += 4) {
            float4 a4[4], b4[4];
#pragma unroll
            for (int i = 0; i < 4; i++) a4[i] = *(const float4*)&Ws[(ty + 16 * i) * 16 + c4];
#pragma unroll
            for (int e = 0; e < 4; e++) b4[e] = *(const float4*)&Xs[(c4 + e) * 64 + tx * 4];
#pragma unroll
            for (int i = 0; i < 4; i++) {
                const float* qa = (const float*)&a4[i];
#pragma unroll
                for (int e = 0; e < 4; e++) {
                    const float* bb = (const float*)&b4[e];
                    float a = qa[e];
                    acc[i][0] += a * bb[0];
                    acc[i][1] += a * bb[1];
                    acc[i][2] += a * bb[2];
                    acc[i][3] += a * bb[3];
                }
            }
        }
    }

    __syncthreads();
#pragma unroll
    for (int i = 0; i < 4; i++) {
        float bi = bias[o0 + ty + 16 * i];
#pragma unroll
        for (int j = 0; j < 4; j++)
            stage[(tx * 4 + j) * 68 + ty + 16 * i] = rnd_tf32(acc[i][j] + bi);
    }
    __syncthreads();
    for (int it = 0; it < 4; it++) {
        int idx = tid + 256 * it;
        int n = idx >> 4, o4 = (idx & 15) * 4;
        *(float4*)&dst[(size_t)(n0 + n) * NC + o0 + o4] = *(const float4*)&stage[n * 68 + o4];
    }
}

// ---------------------------------------------------------------------------
// mma.sync tf32 flash attention. 128 CTAs = 8b x 16 qtiles(64). 256 threads.
// Warps: mt = wid&3 (16-row m-tile), half = wid>>2 (key/channel half).
// ---------------------------------------------------------------------------
#define QSTR 260
#define KSTR 260
#define VSTR 264
#define PSTR 68
#define TSTR 68

#define SM_Q    0
#define SM_K    (64 * QSTR)                 // 16640
#define SM_V    (SM_K + 64 * KSTR)          // 33280
#define SM_P    (SM_V + 64 * VSTR)          // 50176
#define SM_L    (SM_P + 64 * PSTR)          // 54528
#define SM_TOT  (SM_L + 64)                 // 54592 floats = 218368 B
// stage overlays K..V region (needs 256*68 = 17408 <= 33696)
#define SM_STG  SM_K

__global__ __launch_bounds__(256, 1) void attn_kernel(
    const float* __restrict__ student, float* __restrict__ out)
{
    extern __shared__ float sm[];
    float* Qs   = sm + SM_Q;
    float* Ks   = sm + SM_K;
    float* Vs   = sm + SM_V;
    float* Ps   = sm + SM_P;
    float* lacc = sm + SM_L;
    float* stg  = sm + SM_STG;

    const int tid  = threadIdx.x;
    const int wid  = tid >> 5, lane = tid & 31;
    const int gr   = lane >> 2, j = lane & 3;
    const int mt   = wid & 3;            // m-tile: rows mt*16 .. +15
    const int half = wid >> 2;           // 0/1: key half (S), channel half (PV)
    const int b    = blockIdx.x >> 4;
    const int q0   = (blockIdx.x & 15) * 64;
    const int r0   = mt * 16 + gr;       // fragment row
    const int r1   = r0 + 8;

    const u32* Qu = (const u32*)Qs;
    const u32* Ku = (const u32*)Ks;
    const u32* Vu = (const u32*)Vs;
    const u32* Pu = (const u32*)Ps;

    // Q fill: [64 q][256 c]
    const float* Qg = g_QpT + ((size_t)b * NN + q0) * NC;
    for (int it = 0; it < 16; it++) {
        int idx = tid + 256 * it;        // 4096 float4
        int r = idx >> 6, c4 = (idx & 63) * 4;
        *(float4*)&Qs[r * QSTR + c4] = *(const float4*)&Qg[(size_t)r * NC + c4];
    }

    const float* stu  = student + (size_t)b * NC * NN;
    float*       outb = out + (size_t)b * NC * NN;

    for (int t = 0; t < NT; t++) {
        const float* Kg = g_KpT + ((size_t)(t * NB + b) * NN) * NC;
        const float* Vg = g_VpT + ((size_t)(t * NB + b) * NN) * NC;

        if (tid < 64) lacc[tid] = 0.0f;

        float oacc[16][4];
#pragma unroll
        for (int f = 0; f < 16; f++)
#pragma unroll
            for (int e = 0; e < 4; e++) oacc[f][e] = 0.0f;

        for (int kt = 0; kt < 16; kt++) {
            __syncthreads();   // buffers free, lacc zeroed visible
            // K tile [64 k][256 c], V tile [64 m][256 c]
            for (int it = 0; it < 16; it++) {
                int idx = tid + 256 * it;
                int r = idx >> 6, c4 = (idx & 63) * 4;
                const float4 kv = *(const float4*)&Kg[(size_t)(kt * 64 + r) * NC + c4];
                const float4 vv = *(const float4*)&Vg[(size_t)(kt * 64 + r) * NC + c4];
                *(float4*)&Ks[r * KSTR + c4] = kv;
                *(float4*)&Vs[r * VSTR + c4] = vv;
            }
            __syncthreads();

            // ---- S = Q K^T : warp does 16q x 32k (keys nb..nb+31) ----
            const int nb = half * 32;
            float sacc[4][4];
#pragma unroll
            for (int f = 0; f < 4; f++)
#pragma unroll
                for (int e = 0; e < 4; e++) sacc[f][e] = 0.0f;

#pragma unroll 4
            for (int kk = 0; kk < 32; kk++) {
                u32 a[4];
                a[0] = Qu[r0 * QSTR + kk * 8 + j];
                a[1] = Qu[r1 * QSTR + kk * 8 + j];
                a[2] = Qu[r0 * QSTR + kk * 8 + j + 4];
                a[3] = Qu[r1 * QSTR + kk * 8 + j + 4];
#pragma unroll
                for (int f = 0; f < 4; f++) {
                    u32 bb[2];
                    int key = nb + 8 * f + gr;
                    bb[0] = Ku[key * KSTR + kk * 8 + j];
                    bb[1] = Ku[key * KSTR + kk * 8 + j + 4];
                    mma_tf32(sacc[f], a, bb);
                }
            }

            // ---- P = exp(S/16), Psm store, row-sum accumulate ----
            float l0 = 0.0f, l1 = 0.0f;
#pragma unroll
            for (int f = 0; f < 4; f++) {
                float p0 = fast_exp(sacc[f][0] * 0.0625f);
                float p1 = fast_exp(sacc[f][1] * 0.0625f);
                float p2 = fast_exp(sacc[f][2] * 0.0625f);
                float p3 = fast_exp(sacc[f][3] * 0.0625f);
                l0 += p0 + p1; l1 += p2 + p3;
                int col = nb + 8 * f + 2 * j;
                *(float2*)&Ps[r0 * PSTR + col] = make_float2(rnd_tf32(p0), rnd_tf32(p1));
                *(float2*)&Ps[r1 * PSTR + col] = make_float2(rnd_tf32(p2), rnd_tf32(p3));
            }
            l0 += __shfl_xor_sync(0xffffffffu, l0, 1);
            l0 += __shfl_xor_sync(0xffffffffu, l0, 2);
            l1 += __shfl_xor_sync(0xffffffffu, l1, 1);
            l1 += __shfl_xor_sync(0xffffffffu, l1, 2);
            if (j == 0) {
                atomicAdd(&lacc[r0], l0);
                atomicAdd(&lacc[r1], l1);
            }
            __syncthreads();   // Psm complete

            // ---- O += P V : warp does 16q x 128c (channels cb..cb+127) ----
            const int cb = half * 128;
#pragma unroll 2
            for (int kk = 0; kk < 8; kk++) {
                u32 a[4];
                a[0] = Pu[r0 * PSTR + kk * 8 + j];
                a[1] = Pu[r1 * PSTR + kk * 8 + j];
                a[2] = Pu[r0 * PSTR + kk * 8 + j + 4];
                a[3] = Pu[r1 * PSTR + kk * 8 + j + 4];
#pragma unroll
                for (int f = 0; f < 16; f++) {
                    u32 bb[2];
                    int c = cb + 8 * f + gr;
                    bb[0] = Vu[(kk * 8 + j) * VSTR + c];
                    bb[1] = Vu[(kk * 8 + j + 4) * VSTR + c];
                    mma_tf32(oacc[f], a, bb);
                }
            }
        } // ktiles

        // ---- epilogue: out += O / (3 l), smem transpose for coalesced RMW ----
        __syncthreads();       // PV done, lacc complete
        float inv0 = 1.0f / (3.0f * lacc[r0]);
        float inv1 = 1.0f / (3.0f * lacc[r1]);
        __syncthreads();       // lacc read before stage overwrites? (separate region) safe
        const int cb = half * 128;
#pragma unroll
        for (int f = 0; f < 16; f++) {
            int c = cb + 8 * f + 2 * j;
            stg[c * TSTR + r0]       = oacc[f][0] * inv0;
            stg[(c + 1) * TSTR + r0] = oacc[f][1] * inv0;
            stg[c * TSTR + r1]       = oacc[f][2] * inv1;
            stg[(c + 1) * TSTR + r1] = oacc[f][3] * inv1;
        }
        __syncthreads();
        for (int it = 0; it < 16; it++) {
            int idx = tid + 256 * it;    // 4096 float4 = 256c x 16 q4
            int c = idx >> 4, q4 = (idx & 15) * 4;
            size_t off = (size_t)c * NN + q0 + q4;
            float4 s4 = *(const float4*)&stg[c * TSTR + q4];
            float4 bs = (t == 0) ? *(const float4*)&stu[off]
                                 : *(const float4*)&outb[off];
            float4 r;
            r.x = bs.x + s4.x; r.y = bs.y + s4.y;
            r.z = bs.z + s4.z; r.w = bs.w + s4.w;
            *(float4*)&outb[off] = r;
        }
        __syncthreads();       // stage consumed before next teacher's K fill
    } // teachers
}

// ---------------------------------------------------------------------------
extern "C" void kernel_launch(void* const* d_in, const int* in_sizes, int n_in,
                              void* d_out, int out_size)
{
    const float* student = (const float*)d_in[0];
    const float* t0 = (const float*)d_in[1];
    const float* t1 = (const float*)d_in[2];
    const float* t2 = (const float*)d_in[3];
    const float* Wq = (const float*)d_in[4];
    const float* bq = (const float*)d_in[5];
    const float* Wk = (const float*)d_in[6];
    const float* bk = (const float*)d_in[7];
    const float* Wv = (const float*)d_in[8];
    const float* bv = (const float*)d_in[9];
    float* out = (float*)d_out;

    dim3 pg(NN / 64, NC / 64, 7 * NB);
    proj_kernel<<<pg, 256>>>(Wq, bq, Wk, bk, Wv, bv, student, t0, t1, t2);

    const int smem_bytes = SM_TOT * 4;
    cudaFuncSetAttribute(attn_kernel, cudaFuncAttributeMaxDynamicSharedMemorySize,
                         smem_bytes);
    attn_kernel<<<NB * (NN / 64), 256, smem_bytes>>>(student, out);
}

// round 7
// speedup vs baseline: 5.4844x; 2.5112x over previous
#include <cuda_runtime.h>
#include <cuda_bf16.h>
#include <cstdint>

typedef uint32_t u32;
typedef uint16_t u16;

#define NB 8
#define NC 256
#define NN 1024
#define NT 3

// bf16 scratch: Q^T/K^T [.., n, c], V [.., c, n]
__device__ u16 g_QpT[NB * NN * NC];
__device__ u16 g_KpT[NT * NB * NN * NC];
__device__ u16 g_Vp [NT * NB * NC * NN];

// ---------------- helpers ----------------
__device__ __forceinline__ u32 to_tf32(float f) {
    u32 r; asm("cvt.rna.tf32.f32 %0, %1;" : "=r"(r) : "f"(f)); return r;
}
__device__ __forceinline__ float rnd_tf32(float f) { return __uint_as_float(to_tf32(f)); }

__device__ __forceinline__ u32 pack_bf16(float lo, float hi) {
    u32 r; asm("cvt.rn.bf16x2.f32 %0, %1, %2;" : "=r"(r) : "f"(hi), "f"(lo)); return r;
}
__device__ __forceinline__ u16 bf16_bits(float f) {
    u16 r; asm("cvt.rn.bf16.f32 %0, %1;" : "=h"(r) : "f"(f)); return r;
}

__device__ __forceinline__ void mma_tf32(float* d, const u32* a, const u32* b) {
    asm volatile(
        "mma.sync.aligned.m16n8k8.row.col.f32.tf32.tf32.f32 "
        "{%0,%1,%2,%3}, {%4,%5,%6,%7}, {%8,%9}, {%0,%1,%2,%3};"
        : "+f"(d[0]), "+f"(d[1]), "+f"(d[2]), "+f"(d[3])
        : "r"(a[0]), "r"(a[1]), "r"(a[2]), "r"(a[3]), "r"(b[0]), "r"(b[1]));
}
__device__ __forceinline__ void mma_bf16(float* d, const u32* a, const u32* b) {
    asm volatile(
        "mma.sync.aligned.m16n8k16.row.col.f32.bf16.bf16.f32 "
        "{%0,%1,%2,%3}, {%4,%5,%6,%7}, {%8,%9}, {%0,%1,%2,%3};"
        : "+f"(d[0]), "+f"(d[1]), "+f"(d[2]), "+f"(d[3])
        : "r"(a[0]), "r"(a[1]), "r"(a[2]), "r"(a[3]), "r"(b[0]), "r"(b[1]));
}

__device__ __forceinline__ float fast_exp(float x) {
    float t = fmaf(x, 1.4426950408889634f, 12582912.0f);
    float n = t - 12582912.0f;
    int   e = __float_as_int(t) << 23;
    float r = fmaf(x, 1.4426950408889634f, -n);
    float p = 1.3333558146e-3f;
    p = fmaf(p, r, 9.6181291076e-3f);
    p = fmaf(p, r, 5.5504108665e-2f);
    p = fmaf(p, r, 2.4022650696e-1f);
    p = fmaf(p, r, 6.9314718056e-1f);
    p = fmaf(p, r, 1.0f);
    return __int_as_float(__float_as_int(p) + e);
}

// ---------------------------------------------------------------------------
// Projection via tf32 mma: Out[o][n] = sum_c W[o][c] X[c][n] + b[o]
// CTA tile 64o x 256n, 8 warps (ow = wid&1, nw = wid>>1), warp 32o x 64n.
// Writes bf16: Q/K transposed ([n][c], via smem stage), V direct ([c][n]).
// Grid: (NN/256, NC/64, 7*8)
// ---------------------------------------------------------------------------
#define PW_STR 36
#define PX_STR 264
#define PSM_BYTES (64 * PW_STR * 4 + 32 * PX_STR * 4)   // 9216 + 33792 = 43008

__global__ __launch_bounds__(256) void proj_kernel(
    const float* __restrict__ Wq, const float* __restrict__ bq,
    const float* __restrict__ Wk, const float* __restrict__ bk,
    const float* __restrict__ Wv, const float* __restrict__ bv,
    const float* __restrict__ xs, const float* __restrict__ x0,
    const float* __restrict__ x1, const float* __restrict__ x2)
{
    __shared__ __align__(16) char psm[PSM_BYTES];
    float* Wsf = (float*)psm;                       // [64][36]
    float* Xsf = (float*)(psm + 64 * PW_STR * 4);   // [32][264]
    u16*   stg = (u16*)psm;                         // overlay: [256 n][72 o] bf16

    const int tid  = threadIdx.x;
    const int wid  = tid >> 5, lane = tid & 31;
    const int gr   = lane >> 2, j = lane & 3;
    const int ow   = wid & 1, nw = wid >> 1;
    const int n0   = blockIdx.x * 256;
    const int o0   = blockIdx.y * 64;
    const int z    = blockIdx.z;
    const int p    = z >> 3, b = z & 7;

    const float* W; const float* bias; const float* X;
    u16* dst; bool vmode;
    if (p == 0) {
        W = Wq; bias = bq; X = xs + (size_t)b * NC * NN;
        dst = g_QpT + (size_t)b * NN * NC; vmode = false;
    } else if (p <= 3) {
        W = Wk; bias = bk;
        const float* tf = (p == 1) ? x0 : ((p == 2) ? x1 : x2);
        X = tf + (size_t)b * NC * NN;
        dst = g_KpT + ((size_t)(p - 1) * NB + b) * NN * NC; vmode = false;
    } else {
        W = Wv; bias = bv;
        const float* tf = (p == 4) ? x0 : ((p == 5) ? x1 : x2);
        X = tf + (size_t)b * NC * NN;
        dst = g_Vp + ((size_t)(p - 4) * NB + b) * NC * NN; vmode = true;
    }

    float d[2][8][4];
#pragma unroll
    for (int mi = 0; mi < 2; mi++)
#pragma unroll
        for (int f = 0; f < 8; f++)
#pragma unroll
            for (int e = 0; e < 4; e++) d[mi][f][e] = 0.0f;

    for (int c0 = 0; c0 < NC; c0 += 32) {
        __syncthreads();
        // W chunk 64o x 32c
#pragma unroll
        for (int it = 0; it < 2; it++) {
            int idx = tid + 256 * it;
            int r = idx >> 3, c4 = (idx & 7) * 4;
            float4 w4 = *(const float4*)&W[(size_t)(o0 + r) * NC + c0 + c4];
            Wsf[r * PW_STR + c4 + 0] = rnd_tf32(w4.x);
            Wsf[r * PW_STR + c4 + 1] = rnd_tf32(w4.y);
            Wsf[r * PW_STR + c4 + 2] = rnd_tf32(w4.z);
            Wsf[r * PW_STR + c4 + 3] = rnd_tf32(w4.w);
        }
        // X chunk 32c x 256n
#pragma unroll
        for (int it = 0; it < 8; it++) {
            int idx = tid + 256 * it;
            int r = idx >> 6, n4 = (idx & 63) * 4;
            float4 x4 = *(const float4*)&X[(size_t)(c0 + r) * NN + n0 + n4];
            Xsf[r * PX_STR + n4 + 0] = rnd_tf32(x4.x);
            Xsf[r * PX_STR + n4 + 1] = rnd_tf32(x4.y);
            Xsf[r * PX_STR + n4 + 2] = rnd_tf32(x4.z);
            Xsf[r * PX_STR + n4 + 3] = rnd_tf32(x4.w);
        }
        __syncthreads();

#pragma unroll
        for (int kx = 0; kx < 4; kx++) {
            int k0 = kx * 8;
            u32 a[2][4];
#pragma unroll
            for (int mi = 0; mi < 2; mi++) {
                int row = ow * 32 + mi * 16 + gr;
                a[mi][0] = __float_as_uint(Wsf[row * PW_STR + k0 + j]);
                a[mi][1] = __float_as_uint(Wsf[(row + 8) * PW_STR + k0 + j]);
                a[mi][2] = __float_as_uint(Wsf[row * PW_STR + k0 + j + 4]);
                a[mi][3] = __float_as_uint(Wsf[(row + 8) * PW_STR + k0 + j + 4]);
            }
#pragma unroll
            for (int f = 0; f < 8; f++) {
                int n = nw * 64 + f * 8 + gr;
                u32 bb[2];
                bb[0] = __float_as_uint(Xsf[(k0 + j) * PX_STR + n]);
                bb[1] = __float_as_uint(Xsf[(k0 + j + 4) * PX_STR + n]);
                mma_tf32(d[0][f], a[0], bb);
                mma_tf32(d[1][f], a[1], bb);
            }
        }
    }

    // epilogue
    float bi[2][2];
#pragma unroll
    for (int mi = 0; mi < 2; mi++) {
        bi[mi][0] = bias[o0 + ow * 32 + mi * 16 + gr];
        bi[mi][1] = bias[o0 + ow * 32 + mi * 16 + gr + 8];
    }

    if (vmode) {
        // direct [c_out][n] bf16 writes (u32 pairs)
#pragma unroll
        for (int mi = 0; mi < 2; mi++) {
            int row0 = o0 + ow * 32 + mi * 16 + gr;
#pragma unroll
            for (int f = 0; f < 8; f++) {
                int n = n0 + nw * 64 + f * 8 + 2 * j;
                *(u32*)&dst[(size_t)row0 * NN + n] =
                    pack_bf16(d[mi][f][0] + bi[mi][0], d[mi][f][1] + bi[mi][0]);
                *(u32*)&dst[(size_t)(row0 + 8) * NN + n] =
                    pack_bf16(d[mi][f][2] + bi[mi][1], d[mi][f][3] + bi[mi][1]);
            }
        }
    } else {
        __syncthreads();
#pragma unroll
        for (int mi = 0; mi < 2; mi++) {
            int row0 = ow * 32 + mi * 16 + gr;
#pragma unroll
            for (int f = 0; f < 8; f++) {
                int n = nw * 64 + f * 8 + 2 * j;
                stg[n * 72 + row0]           = bf16_bits(d[mi][f][0] + bi[mi][0]);
                stg[(n + 1) * 72 + row0]     = bf16_bits(d[mi][f][1] + bi[mi][0]);
                stg[n * 72 + row0 + 8]       = bf16_bits(d[mi][f][2] + bi[mi][1]);
                stg[(n + 1) * 72 + row0 + 8] = bf16_bits(d[mi][f][3] + bi[mi][1]);
            }
        }
        __syncthreads();
        // coalesced copy out: [n][64 o] bf16 rows of 128B
#pragma unroll
        for (int it = 0; it < 8; it++) {
            int idx = tid + 256 * it;              // 2048 int4
            int n = idx >> 3, u = (idx & 7) * 8;
            *(uint4*)&dst[(size_t)(n0 + n) * NC + o0 + u] = *(const uint4*)&stg[n * 72 + u];
        }
    }
}

// ---------------------------------------------------------------------------
// bf16 mma flash attention. 128 CTAs = 8b x 16 qtiles(64). 256 threads, 8 warps.
// ktile = 128. S: warp 32q x 32k (qw=wid&1, kw=wid>>1). PV: warp 32q x 64c.
// smem bf16 strides: Q/K 264 (528B), V/P 136 (272B) -> conflict-free frags.
// ---------------------------------------------------------------------------
#define SM_Q 0
#define SM_K 33792
#define SM_V 101376
#define SM_P 171008
#define SM_L 188416
#define SM_BYTES 188672

__global__ __launch_bounds__(256, 1) void attn_kernel(
    const float* __restrict__ student, float* __restrict__ out)
{
    extern __shared__ __align__(16) char smc[];
    float* lacc = (float*)(smc + SM_L);

    const int tid  = threadIdx.x;
    const int wid  = tid >> 5, lane = tid & 31;
    const int gr   = lane >> 2, j = lane & 3;
    const int qw   = wid & 1, kw = wid >> 1;     // kw doubles as cw for PV
    const int b    = blockIdx.x >> 4;
    const int q0   = (blockIdx.x & 15) * 64;

    // Q fill: 64 x 256 bf16
    const u16* Qg = g_QpT + ((size_t)b * NN + q0) * NC;
#pragma unroll
    for (int it = 0; it < 8; it++) {
        int idx = tid + 256 * it;                // 2048 uint4
        int r = idx >> 5, u = (idx & 31) * 8;
        *(uint4*)(smc + SM_Q + r * 528 + u * 2) = *(const uint4*)&Qg[(size_t)r * NC + u];
    }

    const float* stu  = student + (size_t)b * NC * NN;
    float*       outb = out + (size_t)b * NC * NN;

    for (int t = 0; t < NT; t++) {
        const u16* Kg = g_KpT + ((size_t)(t * NB + b) * NN) * NC;
        const u16* Vg = g_Vp  + ((size_t)(t * NB + b) * NC) * NN;

        if (tid < 64) lacc[tid] = 0.0f;

        float oacc[2][8][4];
#pragma unroll
        for (int mi = 0; mi < 2; mi++)
#pragma unroll
            for (int f = 0; f < 8; f++)
#pragma unroll
                for (int e = 0; e < 4; e++) oacc[mi][f][e] = 0.0f;

        for (int kt = 0; kt < 8; kt++) {
            const int m0 = kt * 128;
            __syncthreads();
            // K tile: 128 keys x 256 c
#pragma unroll
            for (int it = 0; it < 16; it++) {
                int idx = tid + 256 * it;        // 4096 uint4
                int r = idx >> 5, u = (idx & 31) * 8;
                *(uint4*)(smc + SM_K + r * 528 + u * 2) =
                    *(const uint4*)&Kg[(size_t)(m0 + r) * NC + u];
            }
            // V tile: 256 c x 128 m
#pragma unroll
            for (int it = 0; it < 16; it++) {
                int idx = tid + 256 * it;        // 4096 uint4
                int r = idx >> 4, u = (idx & 15) * 8;
                *(uint4*)(smc + SM_V + r * 272 + u * 2) =
                    *(const uint4*)&Vg[(size_t)r * NN + m0 + u];
            }
            __syncthreads();

            // ---- S = Q K^T : warp 32q x 32k ----
            float sacc[2][4][4];
#pragma unroll
            for (int mi = 0; mi < 2; mi++)
#pragma unroll
                for (int f = 0; f < 4; f++)
#pragma unroll
                    for (int e = 0; e < 4; e++) sacc[mi][f][e] = 0.0f;

#pragma unroll 4
            for (int k0 = 0; k0 < 256; k0 += 16) {
                u32 a[2][4];
#pragma unroll
                for (int mi = 0; mi < 2; mi++) {
                    const char* base = smc + SM_Q + (qw * 32 + mi * 16 + gr) * 528 + (k0 + 2 * j) * 2;
                    a[mi][0] = *(const u32*)(base);
                    a[mi][1] = *(const u32*)(base + 8 * 528);
                    a[mi][2] = *(const u32*)(base + 16);
                    a[mi][3] = *(const u32*)(base + 8 * 528 + 16);
                }
#pragma unroll
                for (int f = 0; f < 4; f++) {
                    const char* kb = smc + SM_K + (kw * 32 + f * 8 + gr) * 528 + (k0 + 2 * j) * 2;
                    u32 bb[2];
                    bb[0] = *(const u32*)(kb);
                    bb[1] = *(const u32*)(kb + 16);
                    mma_bf16(sacc[0][f], a[0], bb);
                    mma_bf16(sacc[1][f], a[1], bb);
                }
            }

            // ---- P = exp(S/16) -> bf16, row sums ----
#pragma unroll
            for (int mi = 0; mi < 2; mi++) {
                int r0 = qw * 32 + mi * 16 + gr;
                float rs0 = 0.0f, rs1 = 0.0f;
#pragma unroll
                for (int f = 0; f < 4; f++) {
                    float p0 = fast_exp(sacc[mi][f][0] * 0.0625f);
                    float p1 = fast_exp(sacc[mi][f][1] * 0.0625f);
                    float p2 = fast_exp(sacc[mi][f][2] * 0.0625f);
                    float p3 = fast_exp(sacc[mi][f][3] * 0.0625f);
                    rs0 += p0 + p1; rs1 += p2 + p3;
                    int col = kw * 32 + f * 8 + 2 * j;
                    *(u32*)(smc + SM_P + r0 * 272 + col * 2)       = pack_bf16(p0, p1);
                    *(u32*)(smc + SM_P + (r0 + 8) * 272 + col * 2) = pack_bf16(p2, p3);
                }
                rs0 += __shfl_xor_sync(0xffffffffu, rs0, 1);
                rs0 += __shfl_xor_sync(0xffffffffu, rs0, 2);
                rs1 += __shfl_xor_sync(0xffffffffu, rs1, 1);
                rs1 += __shfl_xor_sync(0xffffffffu, rs1, 2);
                if (j == 0) {
                    atomicAdd(&lacc[r0], rs0);
                    atomicAdd(&lacc[r0 + 8], rs1);
                }
            }
            __syncthreads();

            // ---- O += P V : warp 32q x 64c ----
#pragma unroll 2
            for (int k0 = 0; k0 < 128; k0 += 16) {
                u32 a[2][4];
#pragma unroll
                for (int mi = 0; mi < 2; mi++) {
                    const char* base = smc + SM_P + (qw * 32 + mi * 16 + gr) * 272 + (k0 + 2 * j) * 2;
                    a[mi][0] = *(const u32*)(base);
                    a[mi][1] = *(const u32*)(base + 8 * 272);
                    a[mi][2] = *(const u32*)(base + 16);
                    a[mi][3] = *(const u32*)(base + 8 * 272 + 16);
                }
#pragma unroll
                for (int f = 0; f < 8; f++) {
                    const char* vb = smc + SM_V + (kw * 64 + f * 8 + gr) * 272 + (k0 + 2 * j) * 2;
                    u32 bb[2];
                    bb[0] = *(const u32*)(vb);
                    bb[1] = *(const u32*)(vb + 16);
                    mma_bf16(oacc[0][f], a[0], bb);
                    mma_bf16(oacc[1][f], a[1], bb);
                }
            }
        } // ktiles

        // ---- epilogue: out += O / (3 l) ----
        __syncthreads();
        float* stg = (float*)(smc + SM_K);     // [256 c][68 q] f32 overlay
#pragma unroll
        for (int mi = 0; mi < 2; mi++) {
            int r0 = qw * 32 + mi * 16 + gr;
            float inv0 = 1.0f / (3.0f * lacc[r0]);
            float inv1 = 1.0f / (3.0f * lacc[r0 + 8]);
#pragma unroll
            for (int f = 0; f < 8; f++) {
                int c = kw * 64 + f * 8 + 2 * j;
                stg[c * 68 + r0]           = oacc[mi][f][0] * inv0;
                stg[(c + 1) * 68 + r0]     = oacc[mi][f][1] * inv0;
                stg[c * 68 + r0 + 8]       = oacc[mi][f][2] * inv1;
                stg[(c + 1) * 68 + r0 + 8] = oacc[mi][f][3] * inv1;
            }
        }
        __syncthreads();
#pragma unroll
        for (int it = 0; it < 16; it++) {
            int idx = tid + 256 * it;          // 4096 float4 = 256c x 16 q4
            int c = idx >> 4, q4 = (idx & 15) * 4;
            size_t off = (size_t)c * NN + q0 + q4;
            float4 s4 = *(const float4*)&stg[c * 68 + q4];
            float4 bs = (t == 0) ? *(const float4*)&stu[off]
                                 : *(const float4*)&outb[off];
            float4 r;
            r.x = bs.x + s4.x; r.y = bs.y + s4.y;
            r.z = bs.z + s4.z; r.w = bs.w + s4.w;
            *(float4*)&outb[off] = r;
        }
        __syncthreads();
    } // teachers
}

// ---------------------------------------------------------------------------
extern "C" void kernel_launch(void* const* d_in, const int* in_sizes, int n_in,
                              void* d_out, int out_size)
{
    const float* student = (const float*)d_in[0];
    const float* t0 = (const float*)d_in[1];
    const float* t1 = (const float*)d_in[2];
    const float* t2 = (const float*)d_in[3];
    const float* Wq = (const float*)d_in[4];
    const float* bq = (const float*)d_in[5];
    const float* Wk = (const float*)d_in[6];
    const float* bk = (const float*)d_in[7];
    const float* Wv = (const float*)d_in[8];
    const float* bv = (const float*)d_in[9];
    float* out = (float*)d_out;

    dim3 pg(NN / 256, NC / 64, 7 * NB);
    proj_kernel<<<pg, 256>>>(Wq, bq, Wk, bk, Wv, bv, student, t0, t1, t2);

    cudaFuncSetAttribute(attn_kernel, cudaFuncAttributeMaxDynamicSharedMemorySize,
                         SM_BYTES);
    attn_kernel<<<NB * (NN / 64), 256, SM_BYTES>>>(student, out);
}